// round 15
// baseline (speedup 1.0000x reference)
#include <cuda_runtime.h>
#include <cuda_bf16.h>
#include <cstdint>

typedef unsigned long long ull;

#define TT 512
#define BB 512
#define HH 128
#define G4 512
#define MTOT 262144              // T*B

// ---------------- device-global scratch (no allocations allowed) ------------
__device__ __align__(16) float g_xg[134217728];    // [m][512] gate preacts (m-major)
__device__ __align__(16) float g_h0[33554432];     // [m][H]
__device__ __align__(16) float g_h1[33554432];     // [m][H]
__device__ __align__(16) uint32_t g_wfh[3][32768]; // W_hh hi bf16 A-frags [mt32][kt8][lane32][reg4]
__device__ __align__(16) uint32_t g_wfl[3][32768]; // W_hh lo bf16 A-frags (same layout)
__device__ __align__(16) uint32_t g_wmma[2][4][16384]; // W_ih l1,l2: [ntile][kt8][pair8][lane32][4] hi | +8192 lo
__device__ float g_bias[3][512];                   // b_ih + b_hh

// ---------------- helpers ---------------------------------------------------
__device__ __forceinline__ float sigf(float x) {
    return __fdividef(1.f, 1.f + __expf(-x));
}
__device__ __forceinline__ float tanh_(float x) {
    return 1.f - __fdividef(2.f, 1.f + __expf(2.f * x));
}
__device__ __forceinline__ uint32_t packbf(float x, float y) {
    __nv_bfloat162 t = __floats2bfloat162_rn(x, y);
    return *(uint32_t*)&t;
}
__device__ __forceinline__ void mma_bf16(float* d, const uint32_t* a, const uint32_t* b) {
    asm volatile(
        "mma.sync.aligned.m16n8k16.row.col.f32.bf16.bf16.f32 "
        "{%0,%1,%2,%3}, {%4,%5,%6,%7}, {%8,%9}, {%0,%1,%2,%3};"
        : "+f"(d[0]), "+f"(d[1]), "+f"(d[2]), "+f"(d[3])
        : "r"(a[0]), "r"(a[1]), "r"(a[2]), "r"(a[3]), "r"(b[0]), "r"(b[1]));
}
__device__ __forceinline__ uint32_t smem_u32p(const void* p) {
    uint32_t a;
    asm("{ .reg .u64 t; cvta.to.shared.u64 t, %1; cvt.u32.u64 %0, t; }" : "=r"(a) : "l"(p));
    return a;
}
__device__ __forceinline__ void cpa16(uint32_t dst, const void* src) {
    asm volatile("cp.async.cg.shared.global [%0], [%1], 16;" :: "r"(dst), "l"(src));
}

// ---------------- fused prep: W_hh A-frags + biases + W_ih B-frags ----------
__global__ void prep_all_kernel(const float* __restrict__ whh0, const float* __restrict__ whh1,
                                const float* __restrict__ whh2,
                                const float* __restrict__ wih1, const float* __restrict__ wih2,
                                const float* __restrict__ bih0, const float* __restrict__ bhh0,
                                const float* __restrict__ bih1, const float* __restrict__ bhh1,
                                const float* __restrict__ bih2, const float* __restrict__ bhh2) {
    int idx = blockIdx.x * 256 + threadIdx.x;
    if (idx < 98304) {
        // W_hh -> bf16 hi/lo A-fragment order
        int l = idx >> 15, r = idx & 32767;
        int reg = r & 3, lane = (r >> 2) & 31, kt = (r >> 7) & 7, mt = r >> 10;
        const float* w = (l == 0) ? whh0 : (l == 1) ? whh1 : whh2;
        int g = mt * 16 + (lane >> 2) + 8 * (reg & 1);
        int wrd = (lane & 3) + 4 * (reg >> 1);
        int k = kt * 16 + 2 * wrd;
        float v0 = w[g * HH + k], v1 = w[g * HH + k + 1];
        float h0 = __bfloat162float(__float2bfloat16(v0));
        float h1 = __bfloat162float(__float2bfloat16(v1));
        g_wfh[l][r] = packbf(v0, v1);
        g_wfl[l][r] = packbf(v0 - h0, v1 - h1);
    } else if (idx < 163840) {
        // W_ih (l1,l2) -> bf16 hi/lo B-frags, ntt-PAIRED layout
        int r2 = idx - 98304;
        int p = r2 >> 15; r2 &= 32767;
        int j = r2 >> 6, kw = r2 & 63;
        const float* w = p ? wih2 : wih1;
        float2 v = *(const float2*)(w + j * HH + 2 * kw);
        float xh = __bfloat162float(__float2bfloat16(v.x));
        float yh = __bfloat162float(__float2bfloat16(v.y));
        uint32_t wh = packbf(v.x, v.y);
        uint32_t wl = packbf(v.x - xh, v.y - yh);
        int ntile = j >> 7, n = j & 127;
        int ntt = n >> 3, nr = n & 7;
        int pair = ntt >> 1, odd = ntt & 1;
        int kt = kw >> 3, wi = kw & 7, w3 = wi & 3, reg = wi >> 2;
        uint32_t dst = (uint32_t)(((kt * 8 + pair) * 32 + nr * 4 + w3) * 4 + odd * 2 + reg);
        g_wmma[p][ntile][dst] = wh;
        g_wmma[p][ntile][8192 + dst] = wl;
    } else if (idx < 165376) {
        int r = idx - 163840;
        int l = r >> 9, j = r & 511;
        const float* bi = (l == 0) ? bih0 : (l == 1) ? bih1 : bih2;
        const float* bh = (l == 0) ? bhh0 : (l == 1) ? bhh1 : bhh2;
        g_bias[l][j] = bi[j] + bh[j];
    }
}

// ---------------- layer-0 input projection (K = 8), m-major output -----------
__global__ __launch_bounds__(256) void proj0_kernel(const float* __restrict__ x,
                                                    const float* __restrict__ w0) {
    __shared__ float ws[4096], xs[4096], bs[512];
    int t = blockIdx.x, tid = threadIdx.x;
    for (int i = tid; i < 4096; i += 256) ws[i] = w0[i];
    for (int i = tid; i < 512; i += 256) bs[i] = g_bias[0][i];
    for (int i = tid; i < 4096; i += 256) {
        int b = i >> 3, f = i & 7;
        xs[i] = x[(size_t)b * 4096 + t * 8 + f];
    }
    __syncthreads();
    int j0 = tid, j1 = tid + 256;
    float w0r[8], w1r[8];
#pragma unroll
    for (int f = 0; f < 8; f++) { w0r[f] = ws[j0 * 8 + f]; w1r[f] = ws[j1 * 8 + f]; }
    float bz0 = bs[j0], bz1 = bs[j1];
    float* outt = g_xg + (size_t)t * BB * G4;
    for (int b = 0; b < BB; b++) {
        float a0 = bz0, a1 = bz1;
#pragma unroll
        for (int f = 0; f < 8; f++) {
            float xv = xs[b * 8 + f];
            a0 = fmaf(xv, w0r[f], a0);
            a1 = fmaf(xv, w1r[f], a1);
        }
        outt[(size_t)b * G4 + j0] = a0;
        outt[(size_t)b * G4 + j1] = a1;
    }
}

// ---------------- recurrent LSTM on tensor cores ------------------------------
// 128 CTAs x 512 thr. Alo smem holds ONLY kt 2..7 (kt 0,1 in regs): 96 KB.
#define RSM_BSM 98304            // B frags: 2KB
#define RSM_GSM 100352           // [4 b][512 g] f32 = 8KB
#define RSM_TOT 108544

__global__ __launch_bounds__(512, 1) void rec2_kernel(int l, int outsel) {
    extern __shared__ char sm[];
    uint32_t* bsm = (uint32_t*)(sm + RSM_BSM);
    float* gsm = (float*)(sm + RSM_GSM);
    int tid = threadIdx.x, lane = tid & 31, wv = tid >> 5;
    int b0 = blockIdx.x * 4;
    float* hout = outsel ? g_h1 : g_h0;

    {   // A-lo frags kt 2..7 -> smem: dst [mtile][kt-2][lane], src [mtile][kt][lane]
        const uint4* s = (const uint4*)g_wfl[l];
        uint4* d = (uint4*)sm;
        for (int i = tid; i < 6144; i += 512) {
            int mtile = i / 192, r0 = i - mtile * 192;
            d[mtile * 192 + r0] = s[mtile * 256 + 64 + r0];
        }
    }
    uint4 ahi[2][8];
#pragma unroll
    for (int mt = 0; mt < 2; mt++)
#pragma unroll
        for (int kt = 0; kt < 8; kt++)
            ahi[mt][kt] = *((const uint4*)g_wfh[l] + (((wv * 2 + mt) * 8 + kt) * 32 + lane));
    uint4 alor[2][2];            // Alo register cache, kt 0..1
#pragma unroll
    for (int mt = 0; mt < 2; mt++)
#pragma unroll
        for (int kt = 0; kt < 2; kt++)
            alor[mt][kt] = *((const uint4*)g_wfl[l] + (((wv * 2 + mt) * 8 + kt) * 32 + lane));
    if (tid < 512) bsm[tid] = 0;   // h0 = 0 (hi and lo halves)

    int r = lane >> 2, cc = lane & 3;
    int g0 = wv * 32 + r, g1 = g0 + 16;
    int eb = tid >> 7, ehh = tid & 127;
    int ekt = ehh >> 4, ew = (ehh & 15) >> 1, ehalf = ehh & 1;
    uint32_t eoff = (uint32_t)(((ekt * 32 + (eb * 4 + (ew & 3))) * 2 + (ew >> 2)) * 4 + ehalf * 2);
    float cst = 0.f;
    __syncthreads();

    for (int t = 0; t < TT; t++) {
        float xv[8];
        if (cc < 2) {
            const float* xrow = g_xg + ((size_t)t * BB + b0) * G4;
            int b = 2 * cc;
            xv[0] = xrow[b * G4 + g0];       xv[1] = xrow[(b + 1) * G4 + g0];
            xv[2] = xrow[b * G4 + g0 + 8];   xv[3] = xrow[(b + 1) * G4 + g0 + 8];
            xv[4] = xrow[b * G4 + g1];       xv[5] = xrow[(b + 1) * G4 + g1];
            xv[6] = xrow[b * G4 + g1 + 8];   xv[7] = xrow[(b + 1) * G4 + g1 + 8];
        }
        float acc[2][4];
#pragma unroll
        for (int mt = 0; mt < 2; mt++)
#pragma unroll
            for (int i = 0; i < 4; i++) acc[mt][i] = 0.f;
#pragma unroll
        for (int kt = 0; kt < 8; kt++) {
            uint2 bh = *(const uint2*)&bsm[kt * 64 + lane * 2];
#pragma unroll
            for (int mt = 0; mt < 2; mt++) {
                uint4 alo;
                if (kt < 2) alo = alor[mt][kt];
                else        alo = *((const uint4*)sm + (((wv * 2 + mt) * 6 + (kt - 2)) * 32 + lane));
                mma_bf16(acc[mt], (const uint32_t*)&ahi[mt][kt], (const uint32_t*)&bh);
                mma_bf16(acc[mt], (const uint32_t*)&alo, (const uint32_t*)&bh);
            }
        }
#pragma unroll
        for (int mt = 0; mt < 2; mt++)
#pragma unroll
            for (int i = 0; i < 4; i++)
                acc[mt][i] += __shfl_xor_sync(0xFFFFFFFFu, acc[mt][i], 2);
        if (cc < 2) {
            int b = 2 * cc;
            gsm[b * 512 + g0]           = acc[0][0] + xv[0];
            gsm[(b + 1) * 512 + g0]     = acc[0][1] + xv[1];
            gsm[b * 512 + g0 + 8]       = acc[0][2] + xv[2];
            gsm[(b + 1) * 512 + g0 + 8] = acc[0][3] + xv[3];
            gsm[b * 512 + g1]           = acc[1][0] + xv[4];
            gsm[(b + 1) * 512 + g1]     = acc[1][1] + xv[5];
            gsm[b * 512 + g1 + 8]       = acc[1][2] + xv[6];
            gsm[(b + 1) * 512 + g1 + 8] = acc[1][3] + xv[7];
        }
        __syncthreads();
        {
            const float* gb = gsm + eb * 512;
            float iv = gb[ehh], fv = gb[128 + ehh], gg = gb[256 + ehh], ov = gb[384 + ehh];
            cst = sigf(fv) * cst + sigf(iv) * tanh_(gg);
            float h = sigf(ov) * tanh_(cst);
            hout[((size_t)t * BB + b0 + eb) * HH + ehh] = h;
            __nv_bfloat16 hbh = __float2bfloat16(h);
            __nv_bfloat16 hbl = __float2bfloat16(h - __bfloat162float(hbh));
            *(__nv_bfloat16*)(sm + RSM_BSM + eoff) = hbh;         // n = eb   (hi)
            *(__nv_bfloat16*)(sm + RSM_BSM + eoff + 128) = hbl;   // n = eb+4 (lo)
        }
        __syncthreads();
    }
}

// ---------------- layers 1,2 input projection: mma.sync bf16 3-split GEMM ----
// 2048 CTAs x 128 m-rows; 512 thr = 16 warps (4 mw x 4 nh), warp 32m x 32n.
// A loaded once per CTA; B double-buffered via cp.async; B frags ntt-paired
// so each B fetch is one lds.128 covering 2 n8-tiles.
#define PA_LO 8192
#define PB0   16384
#define PB1   32768
#define PBIAS 49152
#define SMW_TOT ((49152 + 512) * 4)

__global__ __launch_bounds__(512, 1) void proj_mma_kernel(int p) {
    extern __shared__ uint32_t smw[];
    float* bias = (float*)(smw + PBIAS);
    uint32_t sbase = smem_u32p(smw);
    int tid = threadIdx.x;
    int wid = tid >> 5, lane = tid & 31;
    int mw = wid & 3, nh = wid >> 2;
    const float* hin = p ? g_h1 : g_h0;
    int mbase = blockIdx.x * 128;

    // prefetch B(nt=0) into buf0 via cp.async (overlaps with A loads below)
#pragma unroll
    for (int it = 0; it < 8; it++) {
        int idx = it * 512 + tid;
        cpa16(sbase + (PB0 + idx * 4) * 4, &g_wmma[p][0][idx * 4]);
    }
    asm volatile("cp.async.commit_group;");

    if (tid < 512) bias[tid] = g_bias[p + 1][tid];
    // A: load h rows (fp32), split hi/lo bf16 into fragment-order smem
#pragma unroll
    for (int it = 0; it < 16; it++) {
        int idx = it * 512 + tid;
        int m = idx >> 6, kw = idx & 63;
        float2 v = *(const float2*)(hin + (size_t)(mbase + m) * HH + 2 * kw);
        float xh = __bfloat162float(__float2bfloat16(v.x));
        float yh = __bfloat162float(__float2bfloat16(v.y));
        uint32_t whw = packbf(v.x, v.y);
        uint32_t wlw = packbf(v.x - xh, v.y - yh);
        int mt = m >> 4, row = m & 15, hb = row >> 3, r = row & 7;
        int kt = kw >> 3, wi = kw & 7, w3 = wi & 3, wh2 = wi >> 2;
        uint32_t dst = (uint32_t)(((mt * 8 + kt) * 32 + r * 4 + w3) * 4 + hb + 2 * wh2);
        smw[dst] = whw;
        smw[PA_LO + dst] = wlw;
    }

    for (int nt = 0; nt < 4; nt++) {
        int nbase = nt * 128;
        uint32_t bbase = (nt & 1) ? PB1 : PB0;
        __syncthreads();   // prior mma done reading the buffer we now overwrite
        if (nt < 3) {
            uint32_t nxt = ((nt + 1) & 1) ? PB1 : PB0;
#pragma unroll
            for (int it = 0; it < 8; it++) {
                int idx = it * 512 + tid;
                cpa16(sbase + (nxt + idx * 4) * 4, &g_wmma[p][nt + 1][idx * 4]);
            }
            asm volatile("cp.async.commit_group;");
            asm volatile("cp.async.wait_group 1;");
        } else {
            asm volatile("cp.async.wait_group 0;");
        }
        __syncthreads();   // B(nt) visible (and A on first iter)

        float acc[2][4][4];
#pragma unroll
        for (int mt = 0; mt < 2; mt++)
#pragma unroll
            for (int n2 = 0; n2 < 4; n2++)
#pragma unroll
                for (int i = 0; i < 4; i++) acc[mt][n2][i] = 0.f;

#pragma unroll
        for (int kt = 0; kt < 8; kt++) {
            uint4 ah[2], al[2];
#pragma unroll
            for (int mt = 0; mt < 2; mt++) {
                int mtile = mw * 2 + mt;
                ah[mt] = *((const uint4*)smw + ((mtile * 8 + kt) * 32 + lane));
                al[mt] = *((const uint4*)(smw + PA_LO) + ((mtile * 8 + kt) * 32 + lane));
            }
            uint2 bh[4], bl[4];
#pragma unroll
            for (int p2 = 0; p2 < 2; p2++) {
                uint4 bb = *((const uint4*)(smw + bbase) + ((kt * 8 + nh * 2 + p2) * 32 + lane));
                bh[2 * p2]     = make_uint2(bb.x, bb.y);
                bh[2 * p2 + 1] = make_uint2(bb.z, bb.w);
                uint4 bb2 = *((const uint4*)(smw + bbase + 8192) + ((kt * 8 + nh * 2 + p2) * 32 + lane));
                bl[2 * p2]     = make_uint2(bb2.x, bb2.y);
                bl[2 * p2 + 1] = make_uint2(bb2.z, bb2.w);
            }
#pragma unroll
            for (int mt = 0; mt < 2; mt++)
#pragma unroll
                for (int n2 = 0; n2 < 4; n2++) {
                    mma_bf16(acc[mt][n2], (const uint32_t*)&ah[mt], (const uint32_t*)&bh[n2]);
                    mma_bf16(acc[mt][n2], (const uint32_t*)&al[mt], (const uint32_t*)&bh[n2]);
                    mma_bf16(acc[mt][n2], (const uint32_t*)&ah[mt], (const uint32_t*)&bl[n2]);
                }
        }

        int r = lane >> 2, cc = lane & 3;
#pragma unroll
        for (int mt = 0; mt < 2; mt++) {
            int m0 = mbase + mw * 32 + mt * 16 + r;
#pragma unroll
            for (int n2 = 0; n2 < 4; n2++) {
                int nl = nh * 32 + n2 * 8 + 2 * cc;
                float b0v = bias[nbase + nl], b1v = bias[nbase + nl + 1];
                float2 v0 = make_float2(acc[mt][n2][0] + b0v, acc[mt][n2][1] + b1v);
                float2 v1 = make_float2(acc[mt][n2][2] + b0v, acc[mt][n2][3] + b1v);
                *(float2*)(g_xg + (size_t)m0 * G4 + nbase + nl) = v0;
                *(float2*)(g_xg + (size_t)(m0 + 8) * G4 + nbase + nl) = v1;
            }
        }
    }
}

// ---------------- FC head ----------------------------------------------------
__global__ __launch_bounds__(128) void head_kernel(const float* __restrict__ fc1w,
                                                   const float* __restrict__ fc1b,
                                                   const float* __restrict__ fc2w,
                                                   const float* __restrict__ fc2b,
                                                   float* __restrict__ out) {
    __shared__ float last[128], z[128];
    int b = blockIdx.x, tid = threadIdx.x;
    last[tid] = g_h0[((size_t)(TT - 1) * BB + b) * HH + tid];
    __syncthreads();
    float a = fc1b[tid];
#pragma unroll 4
    for (int k = 0; k < HH; k++) a = fmaf(last[k], fc1w[tid * HH + k], a);
    z[tid] = fmaxf(a, 0.f);
    __syncthreads();
    if (tid < 7) {
        float y = fc2b[tid];
#pragma unroll 4
        for (int k = 0; k < HH; k++) y = fmaf(z[k], fc2w[tid * HH + k], y);
        out[b * 7 + tid] = y;
    }
}

// ---------------- launcher ---------------------------------------------------
extern "C" void kernel_launch(void* const* d_in, const int* in_sizes, int n_in,
                              void* d_out, int out_size) {
    (void)in_sizes; (void)n_in; (void)out_size;
    const float* x    = (const float*)d_in[0];
    const float* wih0 = (const float*)d_in[1];
    const float* whh0 = (const float*)d_in[2];
    const float* bih0 = (const float*)d_in[3];
    const float* bhh0 = (const float*)d_in[4];
    const float* wih1 = (const float*)d_in[5];
    const float* whh1 = (const float*)d_in[6];
    const float* bih1 = (const float*)d_in[7];
    const float* bhh1 = (const float*)d_in[8];
    const float* wih2 = (const float*)d_in[9];
    const float* whh2 = (const float*)d_in[10];
    const float* bih2 = (const float*)d_in[11];
    const float* bhh2 = (const float*)d_in[12];
    const float* fc1w = (const float*)d_in[13];
    const float* fc1b = (const float*)d_in[14];
    const float* fc2w = (const float*)d_in[15];
    const float* fc2b = (const float*)d_in[16];
    float* out = (float*)d_out;

    cudaFuncSetAttribute(rec2_kernel, cudaFuncAttributeMaxDynamicSharedMemorySize, RSM_TOT);
    cudaFuncSetAttribute(proj_mma_kernel, cudaFuncAttributeMaxDynamicSharedMemorySize, SMW_TOT);

    prep_all_kernel<<<646, 256>>>(whh0, whh1, whh2, wih1, wih2,
                                  bih0, bhh0, bih1, bhh1, bih2, bhh2);  // 1
    proj0_kernel<<<512, 256>>>(x, wih0);                                // 2
    rec2_kernel<<<128, 512, RSM_TOT>>>(0, 0);                           // 3 -> g_h0
    proj_mma_kernel<<<2048, 512, SMW_TOT>>>(0);                         // 4 (ncu target)
    rec2_kernel<<<128, 512, RSM_TOT>>>(1, 1);                           // 5 -> g_h1
    proj_mma_kernel<<<2048, 512, SMW_TOT>>>(1);                         // 6
    rec2_kernel<<<128, 512, RSM_TOT>>>(2, 0);                           // 7 -> g_h0
    head_kernel<<<512, 128>>>(fc1w, fc1b, fc2w, fc2b, out);             // 8
}

// round 16
// speedup vs baseline: 1.5203x; 1.5203x over previous
#include <cuda_runtime.h>
#include <cuda_bf16.h>
#include <cstdint>

typedef unsigned long long ull;

#define TT 512
#define BB 512
#define HH 128
#define G4 512
#define MTOT 262144              // T*B

// ---------------- device-global scratch (no allocations allowed) ------------
__device__ __align__(16) float g_xg[134217728];    // [m][512] gate preacts (m-major)
__device__ __align__(16) float g_h0[33554432];     // [m][H]
__device__ __align__(16) float g_h1[33554432];     // [m][H]
__device__ __align__(16) uint32_t g_wfh[3][32768]; // W_hh hi bf16 A-frags [mt32][kt8][lane32][reg4]
__device__ __align__(16) uint32_t g_wfl[3][32768]; // W_hh lo bf16 A-frags (same layout)
__device__ __align__(16) uint32_t g_wmma[2][4][16384]; // W_ih l1,l2: [ntile128][hi|lo] frag words
__device__ float g_bias[3][512];                   // b_ih + b_hh

// ---------------- helpers ---------------------------------------------------
__device__ __forceinline__ float sigf(float x) {
    return __fdividef(1.f, 1.f + __expf(-x));
}
__device__ __forceinline__ float tanh_(float x) {
    return 1.f - __fdividef(2.f, 1.f + __expf(2.f * x));
}
__device__ __forceinline__ uint32_t packbf(float x, float y) {
    __nv_bfloat162 t = __floats2bfloat162_rn(x, y);
    return *(uint32_t*)&t;
}
__device__ __forceinline__ void mma_bf16(float* d, const uint32_t* a, const uint32_t* b) {
    asm volatile(
        "mma.sync.aligned.m16n8k16.row.col.f32.bf16.bf16.f32 "
        "{%0,%1,%2,%3}, {%4,%5,%6,%7}, {%8,%9}, {%0,%1,%2,%3};"
        : "+f"(d[0]), "+f"(d[1]), "+f"(d[2]), "+f"(d[3])
        : "r"(a[0]), "r"(a[1]), "r"(a[2]), "r"(a[3]), "r"(b[0]), "r"(b[1]));
}
__device__ __forceinline__ uint32_t smem_u32p(const void* p) {
    uint32_t a;
    asm("{ .reg .u64 t; cvta.to.shared.u64 t, %1; cvt.u32.u64 %0, t; }" : "=r"(a) : "l"(p));
    return a;
}
__device__ __forceinline__ void cpa16(uint32_t dst, const void* src) {
    asm volatile("cp.async.cg.shared.global [%0], [%1], 16;" :: "r"(dst), "l"(src));
}

// ---------------- fused prep: W_hh A-frags + W_ih B-frags + biases ----------
__global__ void prep_all_kernel(const float* __restrict__ whh0, const float* __restrict__ whh1,
                                const float* __restrict__ whh2,
                                const float* __restrict__ wih1, const float* __restrict__ wih2,
                                const float* __restrict__ bih0, const float* __restrict__ bhh0,
                                const float* __restrict__ bih1, const float* __restrict__ bhh1,
                                const float* __restrict__ bih2, const float* __restrict__ bhh2) {
    int idx = blockIdx.x * 256 + threadIdx.x;
    if (idx < 98304) {
        // W_hh -> bf16 hi/lo A-fragment order
        int l = idx >> 15, r = idx & 32767;
        int reg = r & 3, lane = (r >> 2) & 31, kt = (r >> 7) & 7, mt = r >> 10;
        const float* w = (l == 0) ? whh0 : (l == 1) ? whh1 : whh2;
        int g = mt * 16 + (lane >> 2) + 8 * (reg & 1);
        int wrd = (lane & 3) + 4 * (reg >> 1);
        int k = kt * 16 + 2 * wrd;
        float v0 = w[g * HH + k], v1 = w[g * HH + k + 1];
        float h0 = __bfloat162float(__float2bfloat16(v0));
        float h1 = __bfloat162float(__float2bfloat16(v1));
        g_wfh[l][r] = packbf(v0, v1);
        g_wfl[l][r] = packbf(v0 - h0, v1 - h1);
    } else if (idx < 163840) {
        // W_ih (l1,l2) -> bf16 hi/lo B-fragment order (R14 layout, UNPAIRED)
        int r2 = idx - 98304;
        int p = r2 >> 15; r2 &= 32767;
        int j = r2 >> 6, kw = r2 & 63;
        const float* w = p ? wih2 : wih1;
        float2 v = *(const float2*)(w + j * HH + 2 * kw);
        float xh = __bfloat162float(__float2bfloat16(v.x));
        float yh = __bfloat162float(__float2bfloat16(v.y));
        uint32_t wh = packbf(v.x, v.y);
        uint32_t wl = packbf(v.x - xh, v.y - yh);
        int ntile = j >> 7, n = j & 127;
        int ntt = n >> 3, nr = n & 7;
        int kt = kw >> 3, wi = kw & 7, w3 = wi & 3, reg = wi >> 2;
        uint32_t dst = (uint32_t)(((kt * 16 + ntt) * 32 + nr * 4 + w3) * 2 + reg);
        g_wmma[p][ntile][dst] = wh;
        g_wmma[p][ntile][8192 + dst] = wl;
    } else if (idx < 165376) {
        int r = idx - 163840;
        int l = r >> 9, j = r & 511;
        const float* bi = (l == 0) ? bih0 : (l == 1) ? bih1 : bih2;
        const float* bh = (l == 0) ? bhh0 : (l == 1) ? bhh1 : bhh2;
        g_bias[l][j] = bi[j] + bh[j];
    }
}

// ---------------- layer-0 input projection (K = 8), m-major output -----------
__global__ __launch_bounds__(256) void proj0_kernel(const float* __restrict__ x,
                                                    const float* __restrict__ w0) {
    __shared__ float ws[4096], xs[4096], bs[512];
    int t = blockIdx.x, tid = threadIdx.x;
    for (int i = tid; i < 4096; i += 256) ws[i] = w0[i];
    for (int i = tid; i < 512; i += 256) bs[i] = g_bias[0][i];
    for (int i = tid; i < 4096; i += 256) {
        int b = i >> 3, f = i & 7;
        xs[i] = x[(size_t)b * 4096 + t * 8 + f];
    }
    __syncthreads();
    int j0 = tid, j1 = tid + 256;
    float w0r[8], w1r[8];
#pragma unroll
    for (int f = 0; f < 8; f++) { w0r[f] = ws[j0 * 8 + f]; w1r[f] = ws[j1 * 8 + f]; }
    float bz0 = bs[j0], bz1 = bs[j1];
    float* outt = g_xg + (size_t)t * BB * G4;
    for (int b = 0; b < BB; b++) {
        float a0 = bz0, a1 = bz1;
#pragma unroll
        for (int f = 0; f < 8; f++) {
            float xv = xs[b * 8 + f];
            a0 = fmaf(xv, w0r[f], a0);
            a1 = fmaf(xv, w1r[f], a1);
        }
        outt[(size_t)b * G4 + j0] = a0;
        outt[(size_t)b * G4 + j1] = a1;
    }
}

// ---------------- layers 1,2 input projection: mma.sync bf16 3-split GEMM ----
// (R14-exact) 2048 CTAs x one 128-row m-half; 512 thr = 16 warps (4mw x 4nh).
// A loaded once per CTA; B double-buffered via cp.async.
#define PA_LO 8192
#define PB0   16384
#define PB1   32768
#define PBIAS 49152
#define SMW_TOT ((49152 + 512) * 4)

__global__ __launch_bounds__(512, 1) void proj_mma_kernel(int p) {
    extern __shared__ uint32_t smw[];
    float* bias = (float*)(smw + PBIAS);
    uint32_t sbase = smem_u32p(smw);
    int tid = threadIdx.x;
    int wid = tid >> 5, lane = tid & 31;
    int mw = wid & 3, nh = wid >> 2;
    const float* hin = p ? g_h1 : g_h0;
    int mbase = blockIdx.x * 128;

    // prefetch B(nt=0) into buf0 via cp.async (overlaps with A loads below)
#pragma unroll
    for (int it = 0; it < 8; it++) {
        int idx = it * 512 + tid;
        cpa16(sbase + (PB0 + idx * 4) * 4, &g_wmma[p][0][idx * 4]);
    }
    asm volatile("cp.async.commit_group;");

    if (tid < 512) bias[tid] = g_bias[p + 1][tid];
    // A: load h rows (fp32), split hi/lo bf16 into fragment-order smem
#pragma unroll
    for (int it = 0; it < 16; it++) {
        int idx = it * 512 + tid;
        int m = idx >> 6, kw = idx & 63;
        float2 v = *(const float2*)(hin + (size_t)(mbase + m) * HH + 2 * kw);
        float xh = __bfloat162float(__float2bfloat16(v.x));
        float yh = __bfloat162float(__float2bfloat16(v.y));
        uint32_t whw = packbf(v.x, v.y);
        uint32_t wlw = packbf(v.x - xh, v.y - yh);
        int mt = m >> 4, row = m & 15, hb = row >> 3, r = row & 7;
        int kt = kw >> 3, wi = kw & 7, w3 = wi & 3, wh2 = wi >> 2;
        uint32_t dst = (uint32_t)(((mt * 8 + kt) * 32 + r * 4 + w3) * 4 + hb + 2 * wh2);
        smw[dst] = whw;
        smw[PA_LO + dst] = wlw;
    }

    for (int nt = 0; nt < 4; nt++) {
        int nbase = nt * 128;
        uint32_t bbase = (nt & 1) ? PB1 : PB0;
        __syncthreads();   // prior mma done reading the buffer we now overwrite
        if (nt < 3) {
            uint32_t nxt = ((nt + 1) & 1) ? PB1 : PB0;
#pragma unroll
            for (int it = 0; it < 8; it++) {
                int idx = it * 512 + tid;
                cpa16(sbase + (nxt + idx * 4) * 4, &g_wmma[p][nt + 1][idx * 4]);
            }
            asm volatile("cp.async.commit_group;");
            asm volatile("cp.async.wait_group 1;");
        } else {
            asm volatile("cp.async.wait_group 0;");
        }
        __syncthreads();   // B(nt) visible (and A on first iter)

        float acc[2][4][4];
#pragma unroll
        for (int mt = 0; mt < 2; mt++)
#pragma unroll
            for (int n2 = 0; n2 < 4; n2++)
#pragma unroll
                for (int i = 0; i < 4; i++) acc[mt][n2][i] = 0.f;

#pragma unroll
        for (int kt = 0; kt < 8; kt++) {
            uint4 ah[2], al[2];
#pragma unroll
            for (int mt = 0; mt < 2; mt++) {
                int mtile = mw * 2 + mt;
                ah[mt] = *((const uint4*)smw + ((mtile * 8 + kt) * 32 + lane));
                al[mt] = *((const uint4*)(smw + PA_LO) + ((mtile * 8 + kt) * 32 + lane));
            }
            uint2 bh[4], bl[4];
#pragma unroll
            for (int n2 = 0; n2 < 4; n2++) {
                int ntt = nh * 4 + n2;
                bh[n2] = *((const uint2*)(smw + bbase) + ((kt * 16 + ntt) * 32 + lane));
                bl[n2] = *((const uint2*)(smw + bbase + 8192) + ((kt * 16 + ntt) * 32 + lane));
            }
#pragma unroll
            for (int mt = 0; mt < 2; mt++)
#pragma unroll
                for (int n2 = 0; n2 < 4; n2++) {
                    mma_bf16(acc[mt][n2], (const uint32_t*)&ah[mt], (const uint32_t*)&bh[n2]);
                    mma_bf16(acc[mt][n2], (const uint32_t*)&al[mt], (const uint32_t*)&bh[n2]);
                    mma_bf16(acc[mt][n2], (const uint32_t*)&ah[mt], (const uint32_t*)&bl[n2]);
                }
        }

        int r = lane >> 2, cc = lane & 3;
#pragma unroll
        for (int mt = 0; mt < 2; mt++) {
            int m0 = mbase + mw * 32 + mt * 16 + r;
#pragma unroll
            for (int n2 = 0; n2 < 4; n2++) {
                int nl = nh * 32 + n2 * 8 + 2 * cc;
                float b0v = bias[nbase + nl], b1v = bias[nbase + nl + 1];
                float2 v0 = make_float2(acc[mt][n2][0] + b0v, acc[mt][n2][1] + b1v);
                float2 v1 = make_float2(acc[mt][n2][2] + b0v, acc[mt][n2][3] + b1v);
                *(float2*)(g_xg + (size_t)m0 * G4 + nbase + nl) = v0;
                *(float2*)(g_xg + (size_t)(m0 + 8) * G4 + nbase + nl) = v1;
            }
        }
    }
}

// ---------------- recurrent LSTM on tensor cores (R14-exact) -----------------
#define RSM_BSM 131072           // B frags: 2KB
#define RSM_GSM 133120           // [4 b][512 g] f32 = 8KB
#define RSM_TOT 141312

__global__ __launch_bounds__(512, 1) void rec2_kernel(int l, int outsel) {
    extern __shared__ char sm[];
    uint32_t* bsm = (uint32_t*)(sm + RSM_BSM);
    float* gsm = (float*)(sm + RSM_GSM);
    int tid = threadIdx.x, lane = tid & 31, wv = tid >> 5;
    int b0 = blockIdx.x * 4;
    float* hout = outsel ? g_h1 : g_h0;

    {   // A-lo frags -> smem (layout identical to global)
        const uint4* s = (const uint4*)g_wfl[l];
        uint4* d = (uint4*)sm;
        for (int i = tid; i < 8192; i += 512) d[i] = s[i];
    }
    uint4 ahi[2][8];
#pragma unroll
    for (int mt = 0; mt < 2; mt++)
#pragma unroll
        for (int kt = 0; kt < 8; kt++)
            ahi[mt][kt] = *((const uint4*)g_wfh[l] + (((wv * 2 + mt) * 8 + kt) * 32 + lane));
    uint4 alor[2][2];            // Alo register cache, kt 0..1
#pragma unroll
    for (int mt = 0; mt < 2; mt++)
#pragma unroll
        for (int kt = 0; kt < 2; kt++)
            alor[mt][kt] = *((const uint4*)g_wfl[l] + (((wv * 2 + mt) * 8 + kt) * 32 + lane));
    if (tid < 512) bsm[tid] = 0;   // h0 = 0 (hi and lo halves)

    int r = lane >> 2, cc = lane & 3;
    int g0 = wv * 32 + r, g1 = g0 + 16;
    int eb = tid >> 7, ehh = tid & 127;
    int ekt = ehh >> 4, ew = (ehh & 15) >> 1, ehalf = ehh & 1;
    uint32_t eoff = (uint32_t)(((ekt * 32 + (eb * 4 + (ew & 3))) * 2 + (ew >> 2)) * 4 + ehalf * 2);
    float cst = 0.f;
    __syncthreads();

    for (int t = 0; t < TT; t++) {
        float xv[8];
        if (cc < 2) {
            const float* xrow = g_xg + ((size_t)t * BB + b0) * G4;
            int b = 2 * cc;
            xv[0] = xrow[b * G4 + g0];       xv[1] = xrow[(b + 1) * G4 + g0];
            xv[2] = xrow[b * G4 + g0 + 8];   xv[3] = xrow[(b + 1) * G4 + g0 + 8];
            xv[4] = xrow[b * G4 + g1];       xv[5] = xrow[(b + 1) * G4 + g1];
            xv[6] = xrow[b * G4 + g1 + 8];   xv[7] = xrow[(b + 1) * G4 + g1 + 8];
        }
        float acc[2][4];
#pragma unroll
        for (int mt = 0; mt < 2; mt++)
#pragma unroll
            for (int i = 0; i < 4; i++) acc[mt][i] = 0.f;
#pragma unroll
        for (int kt = 0; kt < 8; kt++) {
            uint2 bh = *(const uint2*)&bsm[kt * 64 + lane * 2];
#pragma unroll
            for (int mt = 0; mt < 2; mt++) {
                uint4 alo;
                if (kt < 2) alo = alor[mt][kt];
                else        alo = *((const uint4*)sm + (((wv * 2 + mt) * 8 + kt) * 32 + lane));
                mma_bf16(acc[mt], (const uint32_t*)&ahi[mt][kt], (const uint32_t*)&bh);
                mma_bf16(acc[mt], (const uint32_t*)&alo, (const uint32_t*)&bh);
            }
        }
#pragma unroll
        for (int mt = 0; mt < 2; mt++)
#pragma unroll
            for (int i = 0; i < 4; i++)
                acc[mt][i] += __shfl_xor_sync(0xFFFFFFFFu, acc[mt][i], 2);
        if (cc < 2) {
            int b = 2 * cc;
            gsm[b * 512 + g0]           = acc[0][0] + xv[0];
            gsm[(b + 1) * 512 + g0]     = acc[0][1] + xv[1];
            gsm[b * 512 + g0 + 8]       = acc[0][2] + xv[2];
            gsm[(b + 1) * 512 + g0 + 8] = acc[0][3] + xv[3];
            gsm[b * 512 + g1]           = acc[1][0] + xv[4];
            gsm[(b + 1) * 512 + g1]     = acc[1][1] + xv[5];
            gsm[b * 512 + g1 + 8]       = acc[1][2] + xv[6];
            gsm[(b + 1) * 512 + g1 + 8] = acc[1][3] + xv[7];
        }
        __syncthreads();
        {
            const float* gb = gsm + eb * 512;
            float iv = gb[ehh], fv = gb[128 + ehh], gg = gb[256 + ehh], ov = gb[384 + ehh];
            cst = sigf(fv) * cst + sigf(iv) * tanh_(gg);
            float h = sigf(ov) * tanh_(cst);
            hout[((size_t)t * BB + b0 + eb) * HH + ehh] = h;
            __nv_bfloat16 hbh = __float2bfloat16(h);
            __nv_bfloat16 hbl = __float2bfloat16(h - __bfloat162float(hbh));
            *(__nv_bfloat16*)(sm + RSM_BSM + eoff) = hbh;         // n = eb   (hi)
            *(__nv_bfloat16*)(sm + RSM_BSM + eoff + 128) = hbl;   // n = eb+4 (lo)
        }
        __syncthreads();
    }
}

// ---------------- FC head ----------------------------------------------------
__global__ __launch_bounds__(128) void head_kernel(const float* __restrict__ fc1w,
                                                   const float* __restrict__ fc1b,
                                                   const float* __restrict__ fc2w,
                                                   const float* __restrict__ fc2b,
                                                   float* __restrict__ out) {
    __shared__ float last[128], z[128];
    int b = blockIdx.x, tid = threadIdx.x;
    last[tid] = g_h0[((size_t)(TT - 1) * BB + b) * HH + tid];
    __syncthreads();
    float a = fc1b[tid];
#pragma unroll 4
    for (int k = 0; k < HH; k++) a = fmaf(last[k], fc1w[tid * HH + k], a);
    z[tid] = fmaxf(a, 0.f);
    __syncthreads();
    if (tid < 7) {
        float y = fc2b[tid];
#pragma unroll 4
        for (int k = 0; k < HH; k++) y = fmaf(z[k], fc2w[tid * HH + k], y);
        out[b * 7 + tid] = y;
    }
}

// ---------------- launcher ---------------------------------------------------
extern "C" void kernel_launch(void* const* d_in, const int* in_sizes, int n_in,
                              void* d_out, int out_size) {
    (void)in_sizes; (void)n_in; (void)out_size;
    const float* x    = (const float*)d_in[0];
    const float* wih0 = (const float*)d_in[1];
    const float* whh0 = (const float*)d_in[2];
    const float* bih0 = (const float*)d_in[3];
    const float* bhh0 = (const float*)d_in[4];
    const float* wih1 = (const float*)d_in[5];
    const float* whh1 = (const float*)d_in[6];
    const float* bih1 = (const float*)d_in[7];
    const float* bhh1 = (const float*)d_in[8];
    const float* wih2 = (const float*)d_in[9];
    const float* whh2 = (const float*)d_in[10];
    const float* bih2 = (const float*)d_in[11];
    const float* bhh2 = (const float*)d_in[12];
    const float* fc1w = (const float*)d_in[13];
    const float* fc1b = (const float*)d_in[14];
    const float* fc2w = (const float*)d_in[15];
    const float* fc2b = (const float*)d_in[16];
    float* out = (float*)d_out;

    cudaFuncSetAttribute(rec2_kernel, cudaFuncAttributeMaxDynamicSharedMemorySize, RSM_TOT);
    cudaFuncSetAttribute(proj_mma_kernel, cudaFuncAttributeMaxDynamicSharedMemorySize, SMW_TOT);

    prep_all_kernel<<<646, 256>>>(whh0, whh1, whh2, wih1, wih2,
                                  bih0, bhh0, bih1, bhh1, bih2, bhh2);  // 1
    proj0_kernel<<<512, 256>>>(x, wih0);                                // 2
    rec2_kernel<<<128, 512, RSM_TOT>>>(0, 0);                           // 3 -> g_h0
    proj_mma_kernel<<<2048, 512, SMW_TOT>>>(0);                         // 4 (ncu target)
    rec2_kernel<<<128, 512, RSM_TOT>>>(1, 1);                           // 5 -> g_h1
    proj_mma_kernel<<<2048, 512, SMW_TOT>>>(1);                         // 6
    rec2_kernel<<<128, 512, RSM_TOT>>>(2, 0);                           // 7 -> g_h0
    head_kernel<<<512, 128>>>(fc1w, fc1b, fc2w, fc2b, out);             // 8
}

// round 17
// speedup vs baseline: 1.5724x; 1.0343x over previous
#include <cuda_runtime.h>
#include <cuda_bf16.h>
#include <cstdint>

typedef unsigned long long ull;

#define TT 512
#define BB 512
#define HH 128
#define G4 512
#define MTOT 262144              // T*B

// ---------------- device-global scratch (no allocations allowed) ------------
__device__ __align__(16) float g_xg[134217728];    // [m][512] gate preacts (m-major)
__device__ __align__(16) float g_h0[33554432];     // [m][H]
__device__ __align__(16) float g_h1[33554432];     // [m][H]
__device__ __align__(16) uint32_t g_wfh[3][32768]; // W_hh hi bf16 A-frags [mt32][kt8][lane32][reg4]
__device__ __align__(16) uint32_t g_wfl[3][32768]; // W_hh lo bf16 A-frags (same layout)
__device__ __align__(16) uint32_t g_wmma[2][4][16384]; // W_ih l1,l2: [ntile128][hi|lo] frag words
__device__ float g_bias[3][512];                   // b_ih + b_hh

// ---------------- helpers ---------------------------------------------------
__device__ __forceinline__ float sigf(float x) {
    return __fdividef(1.f, 1.f + __expf(-x));
}
__device__ __forceinline__ float tanha(float x) {
    float y; asm("tanh.approx.f32 %0, %1;" : "=f"(y) : "f"(x)); return y;
}
__device__ __forceinline__ float siga(float x) {
    return fmaf(tanha(0.5f * x), 0.5f, 0.5f);
}
__device__ __forceinline__ uint32_t packbf(float x, float y) {
    __nv_bfloat162 t = __floats2bfloat162_rn(x, y);
    return *(uint32_t*)&t;
}
__device__ __forceinline__ void mma_bf16(float* d, const uint32_t* a, const uint32_t* b) {
    asm volatile(
        "mma.sync.aligned.m16n8k16.row.col.f32.bf16.bf16.f32 "
        "{%0,%1,%2,%3}, {%4,%5,%6,%7}, {%8,%9}, {%0,%1,%2,%3};"
        : "+f"(d[0]), "+f"(d[1]), "+f"(d[2]), "+f"(d[3])
        : "r"(a[0]), "r"(a[1]), "r"(a[2]), "r"(a[3]), "r"(b[0]), "r"(b[1]));
}
__device__ __forceinline__ uint32_t smem_u32p(const void* p) {
    uint32_t a;
    asm("{ .reg .u64 t; cvta.to.shared.u64 t, %1; cvt.u32.u64 %0, t; }" : "=r"(a) : "l"(p));
    return a;
}
__device__ __forceinline__ void cpa16(uint32_t dst, const void* src) {
    asm volatile("cp.async.cg.shared.global [%0], [%1], 16;" :: "r"(dst), "l"(src));
}

// ---------------- fused prep: W_hh A-frags + W_ih B-frags + biases ----------
__global__ void prep_all_kernel(const float* __restrict__ whh0, const float* __restrict__ whh1,
                                const float* __restrict__ whh2,
                                const float* __restrict__ wih1, const float* __restrict__ wih2,
                                const float* __restrict__ bih0, const float* __restrict__ bhh0,
                                const float* __restrict__ bih1, const float* __restrict__ bhh1,
                                const float* __restrict__ bih2, const float* __restrict__ bhh2) {
    int idx = blockIdx.x * 256 + threadIdx.x;
    if (idx < 98304) {
        int l = idx >> 15, r = idx & 32767;
        int reg = r & 3, lane = (r >> 2) & 31, kt = (r >> 7) & 7, mt = r >> 10;
        const float* w = (l == 0) ? whh0 : (l == 1) ? whh1 : whh2;
        int g = mt * 16 + (lane >> 2) + 8 * (reg & 1);
        int wrd = (lane & 3) + 4 * (reg >> 1);
        int k = kt * 16 + 2 * wrd;
        float v0 = w[g * HH + k], v1 = w[g * HH + k + 1];
        float h0 = __bfloat162float(__float2bfloat16(v0));
        float h1 = __bfloat162float(__float2bfloat16(v1));
        g_wfh[l][r] = packbf(v0, v1);
        g_wfl[l][r] = packbf(v0 - h0, v1 - h1);
    } else if (idx < 163840) {
        int r2 = idx - 98304;
        int p = r2 >> 15; r2 &= 32767;
        int j = r2 >> 6, kw = r2 & 63;
        const float* w = p ? wih2 : wih1;
        float2 v = *(const float2*)(w + j * HH + 2 * kw);
        float xh = __bfloat162float(__float2bfloat16(v.x));
        float yh = __bfloat162float(__float2bfloat16(v.y));
        uint32_t wh = packbf(v.x, v.y);
        uint32_t wl = packbf(v.x - xh, v.y - yh);
        int ntile = j >> 7, n = j & 127;
        int ntt = n >> 3, nr = n & 7;
        int kt = kw >> 3, wi = kw & 7, w3 = wi & 3, reg = wi >> 2;
        uint32_t dst = (uint32_t)(((kt * 16 + ntt) * 32 + nr * 4 + w3) * 2 + reg);
        g_wmma[p][ntile][dst] = wh;
        g_wmma[p][ntile][8192 + dst] = wl;
    } else if (idx < 165376) {
        int r = idx - 163840;
        int l = r >> 9, j = r & 511;
        const float* bi = (l == 0) ? bih0 : (l == 1) ? bih1 : bih2;
        const float* bh = (l == 0) ? bhh0 : (l == 1) ? bhh1 : bhh2;
        g_bias[l][j] = bi[j] + bh[j];
    }
}

// ---------------- layer-0 input projection (K = 8), m-major output -----------
__global__ __launch_bounds__(256) void proj0_kernel(const float* __restrict__ x,
                                                    const float* __restrict__ w0) {
    __shared__ float ws[4096], xs[4096], bs[512];
    int t = blockIdx.x, tid = threadIdx.x;
    for (int i = tid; i < 4096; i += 256) ws[i] = w0[i];
    for (int i = tid; i < 512; i += 256) bs[i] = g_bias[0][i];
    for (int i = tid; i < 4096; i += 256) {
        int b = i >> 3, f = i & 7;
        xs[i] = x[(size_t)b * 4096 + t * 8 + f];
    }
    __syncthreads();
    int j0 = tid, j1 = tid + 256;
    float w0r[8], w1r[8];
#pragma unroll
    for (int f = 0; f < 8; f++) { w0r[f] = ws[j0 * 8 + f]; w1r[f] = ws[j1 * 8 + f]; }
    float bz0 = bs[j0], bz1 = bs[j1];
    float* outt = g_xg + (size_t)t * BB * G4;
    for (int b = 0; b < BB; b++) {
        float a0 = bz0, a1 = bz1;
#pragma unroll
        for (int f = 0; f < 8; f++) {
            float xv = xs[b * 8 + f];
            a0 = fmaf(xv, w0r[f], a0);
            a1 = fmaf(xv, w1r[f], a1);
        }
        outt[(size_t)b * G4 + j0] = a0;
        outt[(size_t)b * G4 + j1] = a1;
    }
}

// ---------------- layers 1,2 input projection: mma.sync bf16 3-split GEMM ----
// (R14-exact) 2048 CTAs x one 128-row m-half; 512 thr = 16 warps (4mw x 4nh).
#define PA_LO 8192
#define PB0   16384
#define PB1   32768
#define PBIAS 49152
#define SMW_TOT ((49152 + 512) * 4)

__global__ __launch_bounds__(512, 1) void proj_mma_kernel(int p) {
    extern __shared__ uint32_t smw[];
    float* bias = (float*)(smw + PBIAS);
    uint32_t sbase = smem_u32p(smw);
    int tid = threadIdx.x;
    int wid = tid >> 5, lane = tid & 31;
    int mw = wid & 3, nh = wid >> 2;
    const float* hin = p ? g_h1 : g_h0;
    int mbase = blockIdx.x * 128;

#pragma unroll
    for (int it = 0; it < 8; it++) {
        int idx = it * 512 + tid;
        cpa16(sbase + (PB0 + idx * 4) * 4, &g_wmma[p][0][idx * 4]);
    }
    asm volatile("cp.async.commit_group;");

    if (tid < 512) bias[tid] = g_bias[p + 1][tid];
#pragma unroll
    for (int it = 0; it < 16; it++) {
        int idx = it * 512 + tid;
        int m = idx >> 6, kw = idx & 63;
        float2 v = *(const float2*)(hin + (size_t)(mbase + m) * HH + 2 * kw);
        float xh = __bfloat162float(__float2bfloat16(v.x));
        float yh = __bfloat162float(__float2bfloat16(v.y));
        uint32_t whw = packbf(v.x, v.y);
        uint32_t wlw = packbf(v.x - xh, v.y - yh);
        int mt = m >> 4, row = m & 15, hb = row >> 3, r = row & 7;
        int kt = kw >> 3, wi = kw & 7, w3 = wi & 3, wh2 = wi >> 2;
        uint32_t dst = (uint32_t)(((mt * 8 + kt) * 32 + r * 4 + w3) * 4 + hb + 2 * wh2);
        smw[dst] = whw;
        smw[PA_LO + dst] = wlw;
    }

    for (int nt = 0; nt < 4; nt++) {
        int nbase = nt * 128;
        uint32_t bbase = (nt & 1) ? PB1 : PB0;
        __syncthreads();
        if (nt < 3) {
            uint32_t nxt = ((nt + 1) & 1) ? PB1 : PB0;
#pragma unroll
            for (int it = 0; it < 8; it++) {
                int idx = it * 512 + tid;
                cpa16(sbase + (nxt + idx * 4) * 4, &g_wmma[p][nt + 1][idx * 4]);
            }
            asm volatile("cp.async.commit_group;");
            asm volatile("cp.async.wait_group 1;");
        } else {
            asm volatile("cp.async.wait_group 0;");
        }
        __syncthreads();

        float acc[2][4][4];
#pragma unroll
        for (int mt = 0; mt < 2; mt++)
#pragma unroll
            for (int n2 = 0; n2 < 4; n2++)
#pragma unroll
                for (int i = 0; i < 4; i++) acc[mt][n2][i] = 0.f;

#pragma unroll
        for (int kt = 0; kt < 8; kt++) {
            uint4 ah[2], al[2];
#pragma unroll
            for (int mt = 0; mt < 2; mt++) {
                int mtile = mw * 2 + mt;
                ah[mt] = *((const uint4*)smw + ((mtile * 8 + kt) * 32 + lane));
                al[mt] = *((const uint4*)(smw + PA_LO) + ((mtile * 8 + kt) * 32 + lane));
            }
            uint2 bh[4], bl[4];
#pragma unroll
            for (int n2 = 0; n2 < 4; n2++) {
                int ntt = nh * 4 + n2;
                bh[n2] = *((const uint2*)(smw + bbase) + ((kt * 16 + ntt) * 32 + lane));
                bl[n2] = *((const uint2*)(smw + bbase + 8192) + ((kt * 16 + ntt) * 32 + lane));
            }
#pragma unroll
            for (int mt = 0; mt < 2; mt++)
#pragma unroll
                for (int n2 = 0; n2 < 4; n2++) {
                    mma_bf16(acc[mt][n2], (const uint32_t*)&ah[mt], (const uint32_t*)&bh[n2]);
                    mma_bf16(acc[mt][n2], (const uint32_t*)&al[mt], (const uint32_t*)&bh[n2]);
                    mma_bf16(acc[mt][n2], (const uint32_t*)&ah[mt], (const uint32_t*)&bl[n2]);
                }
        }

        int r = lane >> 2, cc = lane & 3;
#pragma unroll
        for (int mt = 0; mt < 2; mt++) {
            int m0 = mbase + mw * 32 + mt * 16 + r;
#pragma unroll
            for (int n2 = 0; n2 < 4; n2++) {
                int nl = nh * 32 + n2 * 8 + 2 * cc;
                float b0v = bias[nbase + nl], b1v = bias[nbase + nl + 1];
                float2 v0 = make_float2(acc[mt][n2][0] + b0v, acc[mt][n2][1] + b1v);
                float2 v1 = make_float2(acc[mt][n2][2] + b0v, acc[mt][n2][3] + b1v);
                *(float2*)(g_xg + (size_t)m0 * G4 + nbase + nl) = v0;
                *(float2*)(g_xg + (size_t)(m0 + 8) * G4 + nbase + nl) = v1;
            }
        }
    }
}

// ---------------- recurrent LSTM on tensor cores -----------------------------
// tanh.approx gate math (5 MUFU/thread, was 10); store_all=0 elides hout
// stores except the final timestep (layer 2).
#define RSM_BSM 131072           // B frags: 2KB
#define RSM_GSM 133120           // [4 b][512 g] f32 = 8KB
#define RSM_TOT 141312

__global__ __launch_bounds__(512, 1) void rec2_kernel(int l, int outsel, int store_all) {
    extern __shared__ char sm[];
    uint32_t* bsm = (uint32_t*)(sm + RSM_BSM);
    float* gsm = (float*)(sm + RSM_GSM);
    int tid = threadIdx.x, lane = tid & 31, wv = tid >> 5;
    int b0 = blockIdx.x * 4;
    float* hout = outsel ? g_h1 : g_h0;

    {   // A-lo frags -> smem
        const uint4* s = (const uint4*)g_wfl[l];
        uint4* d = (uint4*)sm;
        for (int i = tid; i < 8192; i += 512) d[i] = s[i];
    }
    uint4 ahi[2][8];
#pragma unroll
    for (int mt = 0; mt < 2; mt++)
#pragma unroll
        for (int kt = 0; kt < 8; kt++)
            ahi[mt][kt] = *((const uint4*)g_wfh[l] + (((wv * 2 + mt) * 8 + kt) * 32 + lane));
    uint4 alor[2][2];            // Alo register cache, kt 0..1
#pragma unroll
    for (int mt = 0; mt < 2; mt++)
#pragma unroll
        for (int kt = 0; kt < 2; kt++)
            alor[mt][kt] = *((const uint4*)g_wfl[l] + (((wv * 2 + mt) * 8 + kt) * 32 + lane));
    if (tid < 512) bsm[tid] = 0;   // h0 = 0 (hi and lo halves)

    int r = lane >> 2, cc = lane & 3;
    int g0 = wv * 32 + r, g1 = g0 + 16;
    int eb = tid >> 7, ehh = tid & 127;
    int ekt = ehh >> 4, ew = (ehh & 15) >> 1, ehalf = ehh & 1;
    uint32_t eoff = (uint32_t)(((ekt * 32 + (eb * 4 + (ew & 3))) * 2 + (ew >> 2)) * 4 + ehalf * 2);
    float cst = 0.f;
    __syncthreads();

    for (int t = 0; t < TT; t++) {
        float xv[8];
        if (cc < 2) {
            const float* xrow = g_xg + ((size_t)t * BB + b0) * G4;
            int b = 2 * cc;
            xv[0] = xrow[b * G4 + g0];       xv[1] = xrow[(b + 1) * G4 + g0];
            xv[2] = xrow[b * G4 + g0 + 8];   xv[3] = xrow[(b + 1) * G4 + g0 + 8];
            xv[4] = xrow[b * G4 + g1];       xv[5] = xrow[(b + 1) * G4 + g1];
            xv[6] = xrow[b * G4 + g1 + 8];   xv[7] = xrow[(b + 1) * G4 + g1 + 8];
        }
        float acc[2][4];
#pragma unroll
        for (int mt = 0; mt < 2; mt++)
#pragma unroll
            for (int i = 0; i < 4; i++) acc[mt][i] = 0.f;
#pragma unroll
        for (int kt = 0; kt < 8; kt++) {
            uint2 bh = *(const uint2*)&bsm[kt * 64 + lane * 2];
#pragma unroll
            for (int mt = 0; mt < 2; mt++) {
                uint4 alo;
                if (kt < 2) alo = alor[mt][kt];
                else        alo = *((const uint4*)sm + (((wv * 2 + mt) * 8 + kt) * 32 + lane));
                mma_bf16(acc[mt], (const uint32_t*)&ahi[mt][kt], (const uint32_t*)&bh);
                mma_bf16(acc[mt], (const uint32_t*)&alo, (const uint32_t*)&bh);
            }
        }
#pragma unroll
        for (int mt = 0; mt < 2; mt++)
#pragma unroll
            for (int i = 0; i < 4; i++)
                acc[mt][i] += __shfl_xor_sync(0xFFFFFFFFu, acc[mt][i], 2);
        if (cc < 2) {
            int b = 2 * cc;
            gsm[b * 512 + g0]           = acc[0][0] + xv[0];
            gsm[(b + 1) * 512 + g0]     = acc[0][1] + xv[1];
            gsm[b * 512 + g0 + 8]       = acc[0][2] + xv[2];
            gsm[(b + 1) * 512 + g0 + 8] = acc[0][3] + xv[3];
            gsm[b * 512 + g1]           = acc[1][0] + xv[4];
            gsm[(b + 1) * 512 + g1]     = acc[1][1] + xv[5];
            gsm[b * 512 + g1 + 8]       = acc[1][2] + xv[6];
            gsm[(b + 1) * 512 + g1 + 8] = acc[1][3] + xv[7];
        }
        __syncthreads();
        {
            const float* gb = gsm + eb * 512;
            float iv = gb[ehh], fv = gb[128 + ehh], gg = gb[256 + ehh], ov = gb[384 + ehh];
            cst = siga(fv) * cst + siga(iv) * tanha(gg);
            float h = siga(ov) * tanha(cst);
            if (store_all | (t == TT - 1))
                hout[((size_t)t * BB + b0 + eb) * HH + ehh] = h;
            __nv_bfloat16 hbh = __float2bfloat16(h);
            __nv_bfloat16 hbl = __float2bfloat16(h - __bfloat162float(hbh));
            *(__nv_bfloat16*)(sm + RSM_BSM + eoff) = hbh;         // n = eb   (hi)
            *(__nv_bfloat16*)(sm + RSM_BSM + eoff + 128) = hbl;   // n = eb+4 (lo)
        }
        __syncthreads();
    }
}

// ---------------- FC head ----------------------------------------------------
__global__ __launch_bounds__(128) void head_kernel(const float* __restrict__ fc1w,
                                                   const float* __restrict__ fc1b,
                                                   const float* __restrict__ fc2w,
                                                   const float* __restrict__ fc2b,
                                                   float* __restrict__ out) {
    __shared__ float last[128], z[128];
    int b = blockIdx.x, tid = threadIdx.x;
    last[tid] = g_h0[((size_t)(TT - 1) * BB + b) * HH + tid];
    __syncthreads();
    float a = fc1b[tid];
#pragma unroll 4
    for (int k = 0; k < HH; k++) a = fmaf(last[k], fc1w[tid * HH + k], a);
    z[tid] = fmaxf(a, 0.f);
    __syncthreads();
    if (tid < 7) {
        float y = fc2b[tid];
#pragma unroll 4
        for (int k = 0; k < HH; k++) y = fmaf(z[k], fc2w[tid * HH + k], y);
        out[b * 7 + tid] = y;
    }
}

// ---------------- launcher ---------------------------------------------------
extern "C" void kernel_launch(void* const* d_in, const int* in_sizes, int n_in,
                              void* d_out, int out_size) {
    (void)in_sizes; (void)n_in; (void)out_size;
    const float* x    = (const float*)d_in[0];
    const float* wih0 = (const float*)d_in[1];
    const float* whh0 = (const float*)d_in[2];
    const float* bih0 = (const float*)d_in[3];
    const float* bhh0 = (const float*)d_in[4];
    const float* wih1 = (const float*)d_in[5];
    const float* whh1 = (const float*)d_in[6];
    const float* bih1 = (const float*)d_in[7];
    const float* bhh1 = (const float*)d_in[8];
    const float* wih2 = (const float*)d_in[9];
    const float* whh2 = (const float*)d_in[10];
    const float* bih2 = (const float*)d_in[11];
    const float* bhh2 = (const float*)d_in[12];
    const float* fc1w = (const float*)d_in[13];
    const float* fc1b = (const float*)d_in[14];
    const float* fc2w = (const float*)d_in[15];
    const float* fc2b = (const float*)d_in[16];
    float* out = (float*)d_out;

    cudaFuncSetAttribute(rec2_kernel, cudaFuncAttributeMaxDynamicSharedMemorySize, RSM_TOT);
    cudaFuncSetAttribute(proj_mma_kernel, cudaFuncAttributeMaxDynamicSharedMemorySize, SMW_TOT);

    prep_all_kernel<<<646, 256>>>(whh0, whh1, whh2, wih1, wih2,
                                  bih0, bhh0, bih1, bhh1, bih2, bhh2);  // 1
    proj0_kernel<<<512, 256>>>(x, wih0);                                // 2
    rec2_kernel<<<128, 512, RSM_TOT>>>(0, 0, 1);                        // 3 -> g_h0
    proj_mma_kernel<<<2048, 512, SMW_TOT>>>(0);                         // 4 (ncu target)
    rec2_kernel<<<128, 512, RSM_TOT>>>(1, 1, 1);                        // 5 -> g_h1
    proj_mma_kernel<<<2048, 512, SMW_TOT>>>(1);                         // 6
    rec2_kernel<<<128, 512, RSM_TOT>>>(2, 0, 0);                        // 7 -> g_h0 (only t=511)
    head_kernel<<<512, 128>>>(fc1w, fc1b, fc2w, fc2b, out);             // 8
}